// round 14
// baseline (speedup 1.0000x reference)
#include <cuda_runtime.h>
#include <cuda_bf16.h>
#include <cuda_fp16.h>
#include <cstdint>

#define Mdim 8192          // output rows  (problem N)
#define Cdim 4096          // output cols  (problem K, noise count)
#define Hdim 1024          // reduction dim

#define BM 128
#define BN 128
#define HSTEPS (Hdim / 64)     // 16 stages of 64 cols
#define NSTAGE 3
#define MAT_BYTES 16384        // 128 rows x 64 fp16 (128B rows), one tile
#define STAGE_BYTES (2 * MAT_BYTES)        // Ah, Bh
#define SMEM_TOTAL (NSTAGE * STAGE_BYTES)  // 96 KB -> 2 CTAs/SM
#define NCWARP 8                            // compute warps
#define NTHREADS (32 * (NCWARP + 1))        // + 1 producer warp = 288

// ---------------- static device scratch (no runtime alloc allowed) ----------
// Tile-contiguous, pre-swizzled: tile (rowblk, s) of 128 rows x 64 fp16 cols
// at byte offset ((rowblk*HSTEPS + s) * MAT_BYTES), swizzled 128B rows.
__device__ __align__(16) uint8_t g_ah[(size_t)Mdim * Hdim * 2];
__device__ __align__(16) uint8_t g_bh[(size_t)Cdim * Hdim * 2];
__device__ __align__(16) float g_bn[Cdim];
__device__ __align__(16) float g_pn[Cdim];

// ---------------- helpers ----------------------------------------------------
__device__ __forceinline__ uint32_t smem_u32(const void* p) {
    uint32_t a;
    asm("{ .reg .u64 t; cvta.to.shared.u64 t, %1; cvt.u32.u64 %0, t; }"
        : "=r"(a) : "l"(p));
    return a;
}

#define LDSM4(r, addr) \
    asm volatile("ldmatrix.sync.aligned.m8n8.x4.shared.b16 {%0,%1,%2,%3}, [%4];" \
                 : "=r"((r)[0]), "=r"((r)[1]), "=r"((r)[2]), "=r"((r)[3]) \
                 : "r"(addr))

#define MMA16816(d, a, b0, b1) \
    asm volatile("mma.sync.aligned.m16n8k16.row.col.f32.f16.f16.f32 " \
                 "{%0,%1,%2,%3}, {%4,%5,%6,%7}, {%8,%9}, {%0,%1,%2,%3};" \
                 : "+f"((d)[0]), "+f"((d)[1]), "+f"((d)[2]), "+f"((d)[3]) \
                 : "r"((a)[0]), "r"((a)[1]), "r"((a)[2]), "r"((a)[3]), \
                   "r"(b0), "r"(b1))

__device__ __forceinline__ void mbar_init(uint32_t m, uint32_t cnt) {
    asm volatile("mbarrier.init.shared.b64 [%0], %1;" :: "r"(m), "r"(cnt) : "memory");
}
__device__ __forceinline__ void mbar_expect_tx(uint32_t m, uint32_t bytes) {
    asm volatile("mbarrier.arrive.expect_tx.shared.b64 _, [%0], %1;"
                 :: "r"(m), "r"(bytes) : "memory");
}
__device__ __forceinline__ void mbar_arrive(uint32_t m) {
    asm volatile("mbarrier.arrive.shared.b64 _, [%0];" :: "r"(m) : "memory");
}
__device__ __forceinline__ void wait_parity(uint32_t m, uint32_t ph) {
    asm volatile(
        "{\n\t.reg .pred P;\n\t"
        "WLP_%=:\n\t"
        "mbarrier.try_wait.parity.acquire.cta.shared::cta.b64 P, [%0], %1, 0x989680;\n\t"
        "@P bra.uni WDP_%=;\n\t"
        "bra.uni WLP_%=;\n\t"
        "WDP_%=:\n\t}"
        :: "r"(m), "r"(ph) : "memory");
}
__device__ __forceinline__ void bulk_ld(uint32_t dst, const void* src,
                                        uint32_t bytes, uint32_t mbar) {
    asm volatile(
        "cp.async.bulk.shared::cluster.global.mbarrier::complete_tx::bytes "
        "[%0], [%1], %2, [%3];"
        :: "r"(dst), "l"(src), "r"(bytes), "r"(mbar) : "memory");
}

// tiled + swizzled store of 4 fp16 (8 bytes) for logical (rowblk, r, col4grp)
__device__ __forceinline__ void tile_store(uint8_t* base, int rowblk, int r,
                                           int t, uint2 u) {
    int h = t * 4;                 // starting col in [0,1024)
    int s = h >> 6;                // H-stage tile index
    int c = h & 63;                // col within tile
    size_t blk = ((size_t)(rowblk * HSTEPS + s)) * MAT_BYTES;
    int byte = c * 2;              // 0..127, 8B granularity
    int kc = byte >> 4;            // 16B chunk 0..7
    uint32_t off = (uint32_t)(r * 128 + ((kc ^ (r & 7)) << 4) + (byte & 15));
    *reinterpret_cast<uint2*>(base + blk + off) = u;
}

// ---------------- fused preprocessing -----------------------------------------
__global__ void prep_kernel(const float* __restrict__ input,
                            const float* __restrict__ weight,
                            const float* __restrict__ bias,
                            const float* __restrict__ up,
                            const int* __restrict__ target,
                            const int* __restrict__ noise,
                            float* __restrict__ out_pmt,
                            float* __restrict__ out_pnt) {
    int b = blockIdx.x;
    int t = threadIdx.x;
    if (b < Mdim) {
        float4 v = reinterpret_cast<const float4*>(input + (size_t)b * Hdim)[t];
        __half2 p0 = __halves2half2(__float2half_rn(v.x), __float2half_rn(v.y));
        __half2 p1 = __halves2half2(__float2half_rn(v.z), __float2half_rn(v.w));
        uint2 u;
        u.x = reinterpret_cast<uint32_t&>(p0);
        u.y = reinterpret_cast<uint32_t&>(p1);
        tile_store(g_ah, b >> 7, b & 127, t, u);
    } else if (b < Mdim + Cdim) {
        int k = b - Mdim;
        int v = noise[k];
        float4 w = reinterpret_cast<const float4*>(weight + (size_t)v * Hdim)[t];
        __half2 p0 = __halves2half2(__float2half_rn(w.x), __float2half_rn(w.y));
        __half2 p1 = __halves2half2(__float2half_rn(w.z), __float2half_rn(w.w));
        uint2 u;
        u.x = reinterpret_cast<uint32_t&>(p0);
        u.y = reinterpret_cast<uint32_t&>(p1);
        tile_store(g_bh, k >> 7, k & 127, t, u);
        if (t == 0) { g_bn[k] = bias[v]; g_pn[k] = up[v]; }
    } else {
        int n = (b - Mdim - Cdim) * 8 + (t >> 5);
        int lane = t & 31;
        int tgt = target[n];
        const float4* a = reinterpret_cast<const float4*>(input + (size_t)n * Hdim);
        const float4* w = reinterpret_cast<const float4*>(weight + (size_t)tgt * Hdim);
        float s = 0.f;
#pragma unroll
        for (int j = 0; j < 8; j++) {
            float4 av = a[lane + j * 32];
            float4 wv = w[lane + j * 32];
            s += av.x * wv.x + av.y * wv.y + av.z * wv.z + av.w * wv.w;
        }
#pragma unroll
        for (int o = 16; o; o >>= 1) s += __shfl_xor_sync(0xffffffffu, s, o);
        if (lane == 0) {
            out_pmt[n] = expf(s + bias[tgt]);
            out_pnt[n] = up[tgt];
        }
    }
}

// ---------------- main mma.sync GEMM -------------------------------------------
// pmn[m,c] = __expf(sum_h Ah[m,h]*Bh[c,h] + bn[c]); pnn[m,c] = pn[c].
// 128x128 CTA tile, 8 compute warps of 32x64 + 1 dedicated producer warp,
// 288 threads, 2 CTAs/SM. Producer spins on empty-parity and issues bulk
// loads immediately -> load issue leaves the compute critical path.
//
// Parity protocol: compute warps arrive on all empty[s] once up front, which
// completes empty phase 0. Producer's wait for stage g uses parity
// (g/NSTAGE)&1: g=0..2 -> phase 0 (the initial arrivals), g=3..5 -> phase 1
// (the first in-loop arrivals), etc.
__global__ __launch_bounds__(NTHREADS, 2)
void nce_mma(float* __restrict__ out_pmn, float* __restrict__ out_pnn) {
    extern __shared__ uint8_t dynsm[];
    __shared__ __align__(8) uint64_t barsto[2 * NSTAGE];
    uint32_t smem = smem_u32(dynsm);
    uint32_t bars = smem_u32(barsto);   // full[s]=bars+8s, empty[s]=bars+24+8s

    const int tid = threadIdx.x;
    const int lane = tid & 31;
    const int wid = tid >> 5;

    const int cid = blockIdx.x;
    const int tile_m = cid & 63;      // consecutive CTAs share tile_n -> B reuse
    const int tile_n = cid >> 6;
    const int m0 = tile_m * BM;
    const int c0 = tile_n * BN;

    if (tid == 0) {
#pragma unroll
        for (int s = 0; s < NSTAGE; s++) {
            mbar_init(bars + 8 * s, 1);                // full: tx-based
            mbar_init(bars + 24 + 8 * s, NCWARP);      // empty: 8 warp arrivals
        }
    }
    __syncthreads();

    if (wid == NCWARP) {
        // ---------------- producer warp ----------------
        if (lane == 0) {
            for (int g = 0; g < HSTEPS; g++) {
                int buf = g % NSTAGE;
                wait_parity(bars + 24 + 8 * buf, (uint32_t)((g / NSTAGE) & 1));
                uint32_t fb = bars + 8 * buf;
                mbar_expect_tx(fb, STAGE_BYTES);
                uint32_t dst = smem + buf * STAGE_BYTES;
                bulk_ld(dst, g_ah + ((size_t)(tile_m * HSTEPS + g)) * MAT_BYTES,
                        MAT_BYTES, fb);
                bulk_ld(dst + MAT_BYTES,
                        g_bh + ((size_t)(tile_n * HSTEPS + g)) * MAT_BYTES,
                        MAT_BYTES, fb);
            }
        }
        return;
    }

    // ---------------- compute warps ----------------
    const int wm = wid & 3;           // warp row 0..3  (32 rows each)
    const int wn = wid >> 2;          // warp col 0..1  (64 cols each)
    const int arow0 = wm * 32 + (lane & 15);
    const int achk0 = lane >> 4;
    const int brow0 = wn * 64 + (lane & 7) + ((lane >> 4) & 1) * 8;
    const int bchk0 = (lane >> 3) & 1;

    // free all buffers once -> completes empty phase 0 for the producer
    if (lane == 0) {
#pragma unroll
        for (int s = 0; s < NSTAGE; s++) mbar_arrive(bars + 24 + 8 * s);
    }

    float acc[2][8][4];
#pragma unroll
    for (int i = 0; i < 2; i++)
#pragma unroll
        for (int j = 0; j < 8; j++)
#pragma unroll
            for (int q = 0; q < 4; q++) acc[i][j][q] = 0.f;

    for (int s = 0; s < HSTEPS; s++) {
        int buf = s % NSTAGE;
        wait_parity(bars + 8 * buf, (uint32_t)((s / NSTAGE) & 1));

        uint32_t sb = smem + buf * STAGE_BYTES;
        uint32_t a_h = sb, b_h = sb + MAT_BYTES;

#pragma unroll
        for (int ks = 0; ks < 4; ks++) {
            uint32_t ah[2][4], bh[4][4];
#pragma unroll
            for (int mt = 0; mt < 2; mt++) {
                int row = arow0 + mt * 16;
                int chk = ks * 2 + achk0;
                uint32_t off = row * 128 + ((chk ^ (row & 7)) << 4);
                LDSM4(ah[mt], a_h + off);
            }
#pragma unroll
            for (int bp = 0; bp < 4; bp++) {
                int row = brow0 + bp * 16;
                int chk = ks * 2 + bchk0;
                uint32_t off = row * 128 + ((chk ^ (row & 7)) << 4);
                LDSM4(bh[bp], b_h + off);
            }
#pragma unroll
            for (int mt = 0; mt < 2; mt++)
#pragma unroll
                for (int bp = 0; bp < 4; bp++) {
                    MMA16816(acc[mt][bp * 2 + 0], ah[mt], bh[bp][0], bh[bp][1]);
                    MMA16816(acc[mt][bp * 2 + 1], ah[mt], bh[bp][2], bh[bp][3]);
                }
        }

        if (lane == 0) mbar_arrive(bars + 24 + 8 * buf);
    }

    // ---- epilogue: add bias, exp (MUFU), store ----
    int g = lane >> 2, tg = lane & 3;
#pragma unroll
    for (int bp = 0; bp < 8; bp++) {
        int col = c0 + wn * 64 + bp * 8 + tg * 2;
        float2 bn = *reinterpret_cast<const float2*>(g_bn + col);
        float2 pn = *reinterpret_cast<const float2*>(g_pn + col);
#pragma unroll
        for (int mt = 0; mt < 2; mt++) {
            int r0 = m0 + wm * 32 + mt * 16 + g;
            float2 e0, e1;
            e0.x = __expf(acc[mt][bp][0] + bn.x);
            e0.y = __expf(acc[mt][bp][1] + bn.y);
            e1.x = __expf(acc[mt][bp][2] + bn.x);
            e1.y = __expf(acc[mt][bp][3] + bn.y);
            *reinterpret_cast<float2*>(out_pmn + (size_t)r0 * Cdim + col) = e0;
            *reinterpret_cast<float2*>(out_pmn + (size_t)(r0 + 8) * Cdim + col) = e1;
            *reinterpret_cast<float2*>(out_pnn + (size_t)r0 * Cdim + col) = pn;
            *reinterpret_cast<float2*>(out_pnn + (size_t)(r0 + 8) * Cdim + col) = pn;
        }
    }
}

// ---------------- launch --------------------------------------------------------
extern "C" void kernel_launch(void* const* d_in, const int* in_sizes, int n_in,
                              void* d_out, int out_size) {
    const float* input  = (const float*)d_in[0];
    const float* weight = (const float*)d_in[1];
    const float* bias   = (const float*)d_in[2];
    const float* up     = (const float*)d_in[3];
    const int*   target = (const int*)d_in[4];
    const int*   noise  = (const int*)d_in[5];

    float* out     = (float*)d_out;
    float* out_pmt = out;
    float* out_pnt = out + Mdim;
    float* out_pmn = out + 2 * Mdim;
    float* out_pnn = out_pmn + (size_t)Mdim * Cdim;

    cudaFuncSetAttribute(nce_mma, cudaFuncAttributeMaxDynamicSharedMemorySize,
                         SMEM_TOTAL);

    prep_kernel<<<Mdim + Cdim + Mdim / 8, 256>>>(input, weight, bias, up,
                                                 target, noise, out_pmt, out_pnt);
    nce_mma<<<(Mdim / BM) * (Cdim / BN), NTHREADS, SMEM_TOTAL>>>(out_pmn, out_pnn);
}

// round 16
// speedup vs baseline: 1.1280x; 1.1280x over previous
#include <cuda_runtime.h>
#include <cuda_bf16.h>
#include <cuda_fp16.h>
#include <cstdint>

#define Mdim 8192          // output rows  (problem N)
#define Cdim 4096          // output cols  (problem K, noise count)
#define Hdim 1024          // reduction dim

#define BM 128
#define BN 128
#define HSTEPS (Hdim / 64)     // 16 stages of 64 cols
#define NSTAGE 3
#define MAT_BYTES 16384        // 128 rows x 64 fp16 (128B rows), one tile
#define STAGE_BYTES (2 * MAT_BYTES)        // Ah, Bh
#define SMEM_TOTAL (NSTAGE * STAGE_BYTES)  // 96 KB -> 2 CTAs/SM

// ---------------- static device scratch (no runtime alloc allowed) ----------
// Tile-contiguous, pre-swizzled: tile (rowblk, s) of 128 rows x 64 fp16 cols
// at byte offset ((rowblk*HSTEPS + s) * MAT_BYTES), swizzled 128B rows.
__device__ __align__(16) uint8_t g_ah[(size_t)Mdim * Hdim * 2];
__device__ __align__(16) uint8_t g_bh[(size_t)Cdim * Hdim * 2];
__device__ __align__(16) float g_bn[Cdim];
__device__ __align__(16) float g_pn[Cdim];

// ---------------- helpers ----------------------------------------------------
__device__ __forceinline__ uint32_t smem_u32(const void* p) {
    uint32_t a;
    asm("{ .reg .u64 t; cvta.to.shared.u64 t, %1; cvt.u32.u64 %0, t; }"
        : "=r"(a) : "l"(p));
    return a;
}

#define LDSM4(r, addr) \
    asm volatile("ldmatrix.sync.aligned.m8n8.x4.shared.b16 {%0,%1,%2,%3}, [%4];" \
                 : "=r"((r)[0]), "=r"((r)[1]), "=r"((r)[2]), "=r"((r)[3]) \
                 : "r"(addr))

#define MMA16816(d, a, b0, b1) \
    asm volatile("mma.sync.aligned.m16n8k16.row.col.f32.f16.f16.f32 " \
                 "{%0,%1,%2,%3}, {%4,%5,%6,%7}, {%8,%9}, {%0,%1,%2,%3};" \
                 : "+f"((d)[0]), "+f"((d)[1]), "+f"((d)[2]), "+f"((d)[3]) \
                 : "r"((a)[0]), "r"((a)[1]), "r"((a)[2]), "r"((a)[3]), \
                   "r"(b0), "r"(b1))

__device__ __forceinline__ void mbar_init(uint32_t m, uint32_t cnt) {
    asm volatile("mbarrier.init.shared.b64 [%0], %1;" :: "r"(m), "r"(cnt) : "memory");
}
__device__ __forceinline__ void mbar_expect_tx(uint32_t m, uint32_t bytes) {
    asm volatile("mbarrier.arrive.expect_tx.shared.b64 _, [%0], %1;"
                 :: "r"(m), "r"(bytes) : "memory");
}
__device__ __forceinline__ void mbar_arrive(uint32_t m) {
    asm volatile("mbarrier.arrive.shared.b64 _, [%0];" :: "r"(m) : "memory");
}
__device__ __forceinline__ void wait_parity(uint32_t m, uint32_t ph) {
    asm volatile(
        "{\n\t.reg .pred P;\n\t"
        "WLP_%=:\n\t"
        "mbarrier.try_wait.parity.acquire.cta.shared::cta.b64 P, [%0], %1, 0x989680;\n\t"
        "@P bra.uni WDP_%=;\n\t"
        "bra.uni WLP_%=;\n\t"
        "WDP_%=:\n\t}"
        :: "r"(m), "r"(ph) : "memory");
}
__device__ __forceinline__ void bulk_ld(uint32_t dst, const void* src,
                                        uint32_t bytes, uint32_t mbar) {
    asm volatile(
        "cp.async.bulk.shared::cluster.global.mbarrier::complete_tx::bytes "
        "[%0], [%1], %2, [%3];"
        :: "r"(dst), "l"(src), "r"(bytes), "r"(mbar) : "memory");
}

// pack 8 fp32 -> 8 fp16 in a uint4
__device__ __forceinline__ uint4 cvt8(float4 a, float4 b) {
    __half2 p0 = __halves2half2(__float2half_rn(a.x), __float2half_rn(a.y));
    __half2 p1 = __halves2half2(__float2half_rn(a.z), __float2half_rn(a.w));
    __half2 p2 = __halves2half2(__float2half_rn(b.x), __float2half_rn(b.y));
    __half2 p3 = __halves2half2(__float2half_rn(b.z), __float2half_rn(b.w));
    uint4 u;
    u.x = reinterpret_cast<uint32_t&>(p0);
    u.y = reinterpret_cast<uint32_t&>(p1);
    u.z = reinterpret_cast<uint32_t&>(p2);
    u.w = reinterpret_cast<uint32_t&>(p3);
    return u;
}

// ---------------- preprocessing (coalesced chunk-per-thread) -------------------
// blocks [0, Cdim)          : gather+convert one noise W row (128 threads)
// blocks [Cdim, Cdim+Mdim)  : convert one A row + fused target dot (pmt/pnt)
// Thread t handles stage s = t>>3, chunk kc = t&7 -> one 16B swizzled store;
// 8 consecutive lanes cover a full 128B row (fully coalesced).
__global__ void prep_kernel(const float* __restrict__ input,
                            const float* __restrict__ weight,
                            const float* __restrict__ bias,
                            const float* __restrict__ up,
                            const int* __restrict__ target,
                            const int* __restrict__ noise,
                            float* __restrict__ out_pmt,
                            float* __restrict__ out_pnt) {
    __shared__ float red[4];
    int b = blockIdx.x;
    int t = threadIdx.x;       // 0..127
    int s = t >> 3;            // H-stage 0..15
    int kc = t & 7;            // 16B chunk 0..7

    if (b < Cdim) {
        int k = b;
        int v = noise[k];
        const float* src = weight + (size_t)v * Hdim + s * 64 + kc * 8;
        float4 w0 = *reinterpret_cast<const float4*>(src);
        float4 w1 = *reinterpret_cast<const float4*>(src + 4);
        uint4 u = cvt8(w0, w1);
        int r = k & 127;
        size_t blk = ((size_t)((k >> 7) * HSTEPS + s)) * MAT_BYTES;
        *reinterpret_cast<uint4*>(g_bh + blk + r * 128 + ((kc ^ (r & 7)) << 4)) = u;
        if (t == 0) { g_bn[k] = bias[v]; g_pn[k] = up[v]; }
    } else {
        int n = b - Cdim;
        const float* srca = input + (size_t)n * Hdim + s * 64 + kc * 8;
        float4 a0 = *reinterpret_cast<const float4*>(srca);
        float4 a1 = *reinterpret_cast<const float4*>(srca + 4);
        uint4 u = cvt8(a0, a1);
        int r = n & 127;
        size_t blk = ((size_t)((n >> 7) * HSTEPS + s)) * MAT_BYTES;
        *reinterpret_cast<uint4*>(g_ah + blk + r * 128 + ((kc ^ (r & 7)) << 4)) = u;

        // fused target dot: this block already holds input row n in registers
        int tgt = target[n];
        const float* srcw = weight + (size_t)tgt * Hdim + s * 64 + kc * 8;
        float4 w0 = *reinterpret_cast<const float4*>(srcw);
        float4 w1 = *reinterpret_cast<const float4*>(srcw + 4);
        float d = a0.x * w0.x + a0.y * w0.y + a0.z * w0.z + a0.w * w0.w
                + a1.x * w1.x + a1.y * w1.y + a1.z * w1.z + a1.w * w1.w;
#pragma unroll
        for (int o = 16; o; o >>= 1) d += __shfl_xor_sync(0xffffffffu, d, o);
        if ((t & 31) == 0) red[t >> 5] = d;
        __syncthreads();
        if (t == 0) {
            float ssum = (red[0] + red[1]) + (red[2] + red[3]);
            out_pmt[n] = expf(ssum + bias[tgt]);
            out_pnt[n] = up[tgt];
        }
    }
}

// ---------------- main mma.sync GEMM (r12 verbatim) -----------------------------
// pmn[m,c] = __expf(sum_h Ah[m,h]*Bh[c,h] + bn[c]); pnn[m,c] = pn[c].
// 128x128 CTA tile, 8 warps of 32x64 (4x2 grid), 256 threads, 2 CTAs/SM.
// mbarrier + cp.async.bulk pipeline, no CTA-wide barrier in the mainloop.
__global__ __launch_bounds__(256, 2)
void nce_mma(float* __restrict__ out_pmn, float* __restrict__ out_pnn) {
    extern __shared__ uint8_t dynsm[];
    __shared__ __align__(8) uint64_t barsto[2 * NSTAGE];
    uint32_t smem = smem_u32(dynsm);
    uint32_t bars = smem_u32(barsto);   // full[s]=bars+8s, empty[s]=bars+24+8s

    const int tid = threadIdx.x;
    const int lane = tid & 31;
    const int wid = tid >> 5;
    const int wm = wid & 3;           // warp row 0..3  (32 rows each)
    const int wn = wid >> 2;          // warp col 0..1  (64 cols each)

    const int cid = blockIdx.x;
    const int tile_m = cid & 63;      // consecutive CTAs share tile_n -> B reuse
    const int tile_n = cid >> 6;
    const int m0 = tile_m * BM;
    const int c0 = tile_n * BN;

    const int arow0 = wm * 32 + (lane & 15);
    const int achk0 = lane >> 4;
    const int brow0 = wn * 64 + (lane & 7) + ((lane >> 4) & 1) * 8;
    const int bchk0 = (lane >> 3) & 1;

    if (tid == 0) {
#pragma unroll
        for (int s = 0; s < NSTAGE; s++) {
            mbar_init(bars + 8 * s, 1);                // full: tx-based
            mbar_init(bars + 24 + 8 * s, 8);           // empty: 8 warp arrivals
        }
    }
    __syncthreads();
    if (lane == 0) {
#pragma unroll
        for (int s = 0; s < NSTAGE; s++) mbar_arrive(bars + 24 + 8 * s);
    }

    if (tid == 0) {   // producer priming
#pragma unroll
        for (int p = 0; p < NSTAGE; p++) {
            wait_parity(bars + 24 + 8 * p, 0);
            uint32_t fb = bars + 8 * p;
            mbar_expect_tx(fb, STAGE_BYTES);
            uint32_t dst = smem + p * STAGE_BYTES;
            bulk_ld(dst, g_ah + ((size_t)(tile_m * HSTEPS + p)) * MAT_BYTES,
                    MAT_BYTES, fb);
            bulk_ld(dst + MAT_BYTES,
                    g_bh + ((size_t)(tile_n * HSTEPS + p)) * MAT_BYTES,
                    MAT_BYTES, fb);
        }
    }

    float acc[2][8][4];
#pragma unroll
    for (int i = 0; i < 2; i++)
#pragma unroll
        for (int j = 0; j < 8; j++)
#pragma unroll
            for (int q = 0; q < 4; q++) acc[i][j][q] = 0.f;

    int ph_f = 0;
    int ph_e = 1;

    for (int s = 0; s < HSTEPS; s++) {
        int buf = s % NSTAGE;
        wait_parity(bars + 8 * buf, (uint32_t)ph_f);
        if (buf == NSTAGE - 1) ph_f ^= 1;

        uint32_t sb = smem + buf * STAGE_BYTES;
        uint32_t a_h = sb, b_h = sb + MAT_BYTES;

#pragma unroll
        for (int ks = 0; ks < 4; ks++) {
            uint32_t ah[2][4], bh[4][4];
#pragma unroll
            for (int mt = 0; mt < 2; mt++) {
                int row = arow0 + mt * 16;
                int chk = ks * 2 + achk0;
                uint32_t off = row * 128 + ((chk ^ (row & 7)) << 4);
                LDSM4(ah[mt], a_h + off);
            }
#pragma unroll
            for (int bp = 0; bp < 4; bp++) {
                int row = brow0 + bp * 16;
                int chk = ks * 2 + bchk0;
                uint32_t off = row * 128 + ((chk ^ (row & 7)) << 4);
                LDSM4(bh[bp], b_h + off);
            }
#pragma unroll
            for (int mt = 0; mt < 2; mt++)
#pragma unroll
                for (int bp = 0; bp < 4; bp++) {
                    MMA16816(acc[mt][bp * 2 + 0], ah[mt], bh[bp][0], bh[bp][1]);
                    MMA16816(acc[mt][bp * 2 + 1], ah[mt], bh[bp][2], bh[bp][3]);
                }
        }

        if (lane == 0) mbar_arrive(bars + 24 + 8 * buf);

        if (tid == 0 && s + NSTAGE < HSTEPS) {
            wait_parity(bars + 24 + 8 * buf, (uint32_t)ph_e);
            if (buf == NSTAGE - 1) ph_e ^= 1;
            int p = s + NSTAGE;
            uint32_t fb = bars + 8 * buf;
            mbar_expect_tx(fb, STAGE_BYTES);
            uint32_t dst = smem + buf * STAGE_BYTES;
            bulk_ld(dst, g_ah + ((size_t)(tile_m * HSTEPS + p)) * MAT_BYTES,
                    MAT_BYTES, fb);
            bulk_ld(dst + MAT_BYTES,
                    g_bh + ((size_t)(tile_n * HSTEPS + p)) * MAT_BYTES,
                    MAT_BYTES, fb);
        }
    }

    // ---- epilogue: add bias, exp (MUFU), store ----
    int g = lane >> 2, tg = lane & 3;
#pragma unroll
    for (int bp = 0; bp < 8; bp++) {
        int col = c0 + wn * 64 + bp * 8 + tg * 2;
        float2 bn = *reinterpret_cast<const float2*>(g_bn + col);
        float2 pn = *reinterpret_cast<const float2*>(g_pn + col);
#pragma unroll
        for (int mt = 0; mt < 2; mt++) {
            int r0 = m0 + wm * 32 + mt * 16 + g;
            float2 e0, e1;
            e0.x = __expf(acc[mt][bp][0] + bn.x);
            e0.y = __expf(acc[mt][bp][1] + bn.y);
            e1.x = __expf(acc[mt][bp][2] + bn.x);
            e1.y = __expf(acc[mt][bp][3] + bn.y);
            *reinterpret_cast<float2*>(out_pmn + (size_t)r0 * Cdim + col) = e0;
            *reinterpret_cast<float2*>(out_pmn + (size_t)(r0 + 8) * Cdim + col) = e1;
            *reinterpret_cast<float2*>(out_pnn + (size_t)r0 * Cdim + col) = pn;
            *reinterpret_cast<float2*>(out_pnn + (size_t)(r0 + 8) * Cdim + col) = pn;
        }
    }
}

// ---------------- launch --------------------------------------------------------
extern "C" void kernel_launch(void* const* d_in, const int* in_sizes, int n_in,
                              void* d_out, int out_size) {
    const float* input  = (const float*)d_in[0];
    const float* weight = (const float*)d_in[1];
    const float* bias   = (const float*)d_in[2];
    const float* up     = (const float*)d_in[3];
    const int*   target = (const int*)d_in[4];
    const int*   noise  = (const int*)d_in[5];

    float* out     = (float*)d_out;
    float* out_pmt = out;
    float* out_pnt = out + Mdim;
    float* out_pmn = out + 2 * Mdim;
    float* out_pnn = out_pmn + (size_t)Mdim * Cdim;

    cudaFuncSetAttribute(nce_mma, cudaFuncAttributeMaxDynamicSharedMemorySize,
                         SMEM_TOTAL);

    prep_kernel<<<Cdim + Mdim, 128>>>(input, weight, bias, up, target, noise,
                                      out_pmt, out_pnt);
    nce_mma<<<(Mdim / BM) * (Cdim / BN), 256, SMEM_TOTAL>>>(out_pmn, out_pnn);
}